// round 16
// baseline (speedup 1.0000x reference)
#include <cuda_runtime.h>
#include <cstdint>

// ---------------------------------------------------------------------------
// MoE grouped GEMM: Y[t,o] = sum_k X[t,k] * W[e(t),o,k]
//   X: [1048576,128] f32, W: [16,128,128] f32, expert_size: [16] (i32/i64).
// mma.sync m16n8k8 tf32. 512 threads = 2 INDEPENDENT groups of 8 warps with
// named barriers; groups process interleaved 128-row tiles so one group's
// load-wait/epilogue hides under the other's mma phase. Warp-tile 32x64
// (1.5 smem-words/mma, R13 core). Single A buffer per group (cross-group
// overlap replaces double buffering). W in fragment-order SMEM.
// ---------------------------------------------------------------------------

#define TT   128          // tile rows per group-tile
#define KD   128
#define ND   128
#define KP   132          // padded A stride (floats), conflict-free
#define CPE  64           // CTAs per expert
#define NEXP 16
#define NTHREADS 512

// Bf: [2 wn][16 ks][4 c][32 lane] float4 = 16384 floats (64 KB)
static constexpr int BF_FLOATS   = 2 * 16 * 4 * 32 * 4;
// A: 2 groups x 1 buf x TT x KP
static constexpr int SMEM_FLOATS = BF_FLOATS + 2 * TT * KP;   // 50176 fl = 200704 B

__device__ __forceinline__ uint32_t smem_u32(const void* p) {
    uint32_t a;
    asm("{ .reg .u64 t; cvta.to.shared.u64 t, %1; cvt.u32.u64 %0, t; }" : "=r"(a) : "l"(p));
    return a;
}

__device__ __forceinline__ uint32_t f2tf32(float v) {
    uint32_t r;
    asm("cvt.rn.tf32.f32 %0, %1;" : "=r"(r) : "f"(v));
    return r;
}

__device__ __forceinline__ void cp16(uint32_t dst, const void* src) {
    asm volatile("cp.async.cg.shared.global [%0], [%1], 16;" :: "r"(dst), "l"(src));
}

__device__ __forceinline__ void mma_tf32(float c[4], uint32_t a0, uint32_t a1,
                                         uint32_t a2, uint32_t a3,
                                         uint32_t b0, uint32_t b1) {
    asm volatile(
        "mma.sync.aligned.m16n8k8.row.col.f32.tf32.tf32.f32 "
        "{%0,%1,%2,%3}, {%4,%5,%6,%7}, {%8,%9}, {%0,%1,%2,%3};"
        : "+f"(c[0]), "+f"(c[1]), "+f"(c[2]), "+f"(c[3])
        : "r"(a0), "r"(a1), "r"(a2), "r"(a3), "r"(b0), "r"(b1));
}

__device__ __forceinline__ long long esz_get(const void* esz, int i, bool is64) {
    if (is64) return reinterpret_cast<const long long*>(esz)[i];
    return (long long)reinterpret_cast<const int*>(esz)[i];
}

__global__ void __launch_bounds__(NTHREADS, 1)
moe_mma_kernel(const float* __restrict__ X,
               const float* __restrict__ W,
               const void* __restrict__ expert_size,
               float* __restrict__ Y,
               long long total_tokens)
{
    extern __shared__ float smem[];
    float* Bf = smem;
    float* As = smem + BF_FLOATS;
    const uint32_t Bf_u32 = smem_u32(Bf);

    const int tid  = threadIdx.x;
    const int wid  = tid >> 5;
    const int lane = tid & 31;
    const int g    = lane >> 2;
    const int tig  = lane & 3;

    const int gid  = wid >> 3;              // group 0 / 1
    const int gwid = wid & 7;               // warp within group
    const int gtid = tid & 255;             // thread within group
    const int wm   = gwid >> 1;             // 0..3 (32-row M quarter)
    const int wn   = gwid & 1;              // 0..1 (64-col N half)

    float* Ag = As + gid * (TT * KP);       // group's single A buffer
    const uint32_t Ag_u32 = smem_u32(Ag);

    const int e    = blockIdx.x / CPE;
    const int slot = blockIdx.x % CPE;

    // expert_size dtype sniff (declared i64; JAX x64-off delivers i32).
    const long long probe = reinterpret_cast<const long long*>(expert_size)[0];
    const bool is64 = (probe >= 0 && probe <= total_tokens);

    long long rb = 0;
    for (int i = 0; i < e; i++) rb += esz_get(expert_size, i, is64);
    long long esize = esz_get(expert_size, e, is64);
    if (rb < 0) rb = 0;
    if (rb > total_tokens) rb = total_tokens;
    if (esize < 0) esize = 0;
    if (rb + esize > total_tokens) esize = total_tokens - rb;

    const int etiles = (int)(esize / TT);
    const int q0 = etiles / CPE, r0c = etiles % CPE;
    const int tpc = q0 + (slot < r0c ? 1 : 0);
    const int t0  = slot * q0 + (slot < r0c ? slot : r0c);
    const int gtpc = (tpc - gid + 1) >> 1;          // tiles for this group

    // ---- Stage W_e into FRAGMENT-order SMEM (tf32 RN), all 512 threads ----
    // Entry (vwn, vks, c, l): float4 = {b0(nb=2c), b1(2c), b0(2c+1), b1(2c+1)}
    // with vg=l>>2, vtig=l&3, k=vks*8+vtig, n = vwn*64 + nb*8 + vg.
    if (tpc > 0) {
        const float* wp = W + (size_t)e * ND * KD;
        for (int q = tid; q < 2 * 16 * 4 * 32; q += NTHREADS) {
            int l   = q & 31;
            int c   = (q >> 5) & 3;
            int vks = (q >> 7) & 15;
            int vwn = q >> 11;
            int vg = l >> 2, vtig = l & 3;
            int k  = vks * 8 + vtig;
            int n0 = vwn * 64 + (2 * c) * 8 + vg;
            int n1 = n0 + 8;
            uint32_t f0 = f2tf32(wp[n0 * KD + k]);
            uint32_t f1 = f2tf32(wp[n0 * KD + k + 4]);
            uint32_t f2 = f2tf32(wp[n1 * KD + k]);
            uint32_t f3 = f2tf32(wp[n1 * KD + k + 4]);
            uint32_t a = Bf_u32 + (uint32_t)q * 16u;
            asm volatile("st.shared.v4.b32 [%0], {%1,%2,%3,%4};"
                         :: "r"(a), "r"(f0), "r"(f1), "r"(f2), "r"(f3) : "memory");
        }
    }

    // ---- Group's prefetch of its first tile ----
    if (gtpc > 0) {
        const int tile0 = t0 + gid;
        const float4* xp = reinterpret_cast<const float4*>(
            X + (rb + (long long)tile0 * TT) * KD);
        for (int q = gtid; q < TT * KD / 4; q += 256) {
            int r = q >> 5, c4 = (q & 31) << 2;
            cp16(Ag_u32 + (uint32_t)(r * KP + c4) * 4u, xp + q);
        }
    }
    asm volatile("cp.async.commit_group;" ::: "memory");

    __syncthreads();                        // Bf visible; groups diverge now
    if (gtpc == 0) return;

    const int row_a = wm * 32 + g;
    const int colb0 = wn * 64;
    const uint32_t bf_warp = Bf_u32 + (uint32_t)(wn * 16) * 2048u + (uint32_t)lane * 16u;
    const int bar_id = gid + 1;

    for (int it = 0; it < gtpc; it++) {
        const int tile = t0 + gid + 2 * it;

        asm volatile("cp.async.wait_group 0;" ::: "memory");
        asm volatile("bar.sync %0, 256;" :: "r"(bar_id) : "memory");

        // ---- Compute: warp-tile 32x64 (R13 core) ----
        const float* A0t = Ag + tig;
        float acc[16][4];
        #pragma unroll
        for (int p = 0; p < 16; p++)
            #pragma unroll
            for (int i = 0; i < 4; i++) acc[p][i] = 0.0f;

        #pragma unroll 4
        for (int ks = 0; ks < 16; ks++) {
            const int k = ks * 8;
            uint32_t aF[8];
            #pragma unroll
            for (int mc = 0; mc < 2; mc++) {
                const float* Ar = A0t + (row_a + mc * 16) * KP + k;
                aF[mc * 4 + 0] = f2tf32(Ar[0]);
                aF[mc * 4 + 1] = f2tf32(Ar[8 * KP]);
                aF[mc * 4 + 2] = f2tf32(Ar[4]);
                aF[mc * 4 + 3] = f2tf32(Ar[8 * KP + 4]);
            }
            uint32_t bF[16];
            const uint32_t bks = bf_warp + (uint32_t)ks * 2048u;
            #pragma unroll
            for (int c = 0; c < 4; c++) {
                asm volatile("ld.shared.v4.b32 {%0,%1,%2,%3}, [%4];"
                             : "=r"(bF[c * 4 + 0]), "=r"(bF[c * 4 + 1]),
                               "=r"(bF[c * 4 + 2]), "=r"(bF[c * 4 + 3])
                             : "r"(bks + (uint32_t)c * 512u));
            }
            #pragma unroll
            for (int mc = 0; mc < 2; mc++)
                #pragma unroll
                for (int nb = 0; nb < 8; nb++)
                    mma_tf32(acc[mc * 8 + nb],
                             aF[mc * 4 + 0], aF[mc * 4 + 1],
                             aF[mc * 4 + 2], aF[mc * 4 + 3],
                             bF[nb * 2], bF[nb * 2 + 1]);
        }

        // All group warps done READING A -> safe to overwrite.
        asm volatile("bar.sync %0, 256;" :: "r"(bar_id) : "memory");

        // Prefetch this group's next tile (overlaps epilogue + other group).
        if (it + 1 < gtpc) {
            const int ntile = tile + 2;
            const float4* xp = reinterpret_cast<const float4*>(
                X + (rb + (long long)ntile * TT) * KD);
            for (int q = gtid; q < TT * KD / 4; q += 256) {
                int r = q >> 5, c4 = (q & 31) << 2;
                cp16(Ag_u32 + (uint32_t)(r * KP + c4) * 4u, xp + q);
            }
        }
        asm volatile("cp.async.commit_group;" ::: "memory");

        // ---- Epilogue: st.global.v2 ----
        {
            const long long tile_row = rb + (long long)tile * TT;
            #pragma unroll
            for (int mc = 0; mc < 2; mc++) {
                float* dst0 = Y + (tile_row + row_a + mc * 16)     * ND + colb0 + tig * 2;
                float* dst1 = Y + (tile_row + row_a + mc * 16 + 8) * ND + colb0 + tig * 2;
                #pragma unroll
                for (int nb = 0; nb < 8; nb++) {
                    float2 v0 = make_float2(acc[mc * 8 + nb][0], acc[mc * 8 + nb][1]);
                    float2 v1 = make_float2(acc[mc * 8 + nb][2], acc[mc * 8 + nb][3]);
                    *reinterpret_cast<float2*>(dst0 + nb * 8) = v0;
                    *reinterpret_cast<float2*>(dst1 + nb * 8) = v1;
                }
            }
        }
    }
}

extern "C" void kernel_launch(void* const* d_in, const int* in_sizes, int n_in,
                              void* d_out, int out_size) {
    const float* X   = (const float*)d_in[0];
    const float* W   = (const float*)d_in[1];
    const void*  esz = d_in[2];
    float*       Y   = (float*)d_out;

    const long long total_tokens = (long long)in_sizes[0] / KD;

    cudaFuncSetAttribute(moe_mma_kernel,
                         cudaFuncAttributeMaxDynamicSharedMemorySize,
                         SMEM_FLOATS * (int)sizeof(float));

    moe_mma_kernel<<<NEXP * CPE, NTHREADS, SMEM_FLOATS * (int)sizeof(float)>>>(
        X, W, esz, Y, total_tokens);
}

// round 17
// speedup vs baseline: 1.0405x; 1.0405x over previous
#include <cuda_runtime.h>
#include <cstdint>

// ---------------------------------------------------------------------------
// MoE grouped GEMM: Y[t,o] = sum_k X[t,k] * W[e(t),o,k]
//   X: [1048576,128] f32, W: [16,128,128] f32, expert_size: [16] (i32/i64).
// mma.sync m16n8k8 tf32. 768 threads = 3 INDEPENDENT groups of 8 warps
// (6 warps/SMSP, occ 37.5%) with named barriers; groups process interleaved
// 64-row tiles so stalls in one group hide under the others' mma phases.
// Warp-tile 32x32 (R15 core). Single A buffer per group; prefetch of the
// next tile issues right after the compute-read barrier (R16 pattern).
// W in fragment-order SMEM (B loads = ld.shared.v4).
// ---------------------------------------------------------------------------

#define TT   64           // tile rows per group-tile
#define KD   128
#define ND   128
#define KP   132          // padded A stride (floats), conflict-free
#define CPE  64           // CTAs per expert
#define NEXP 16
#define GROUPS 3
#define NTHREADS 768

// Bf: [4 wn4][16 ks][2 c][32 lane] float4 = 16384 floats (64 KB)
static constexpr int BF_FLOATS   = 4 * 16 * 2 * 32 * 4;
// A: 3 groups x 1 buf x TT x KP
static constexpr int SMEM_FLOATS = BF_FLOATS + GROUPS * TT * KP;  // 166912 B

__device__ __forceinline__ uint32_t smem_u32(const void* p) {
    uint32_t a;
    asm("{ .reg .u64 t; cvta.to.shared.u64 t, %1; cvt.u32.u64 %0, t; }" : "=r"(a) : "l"(p));
    return a;
}

__device__ __forceinline__ uint32_t f2tf32(float v) {
    uint32_t r;
    asm("cvt.rn.tf32.f32 %0, %1;" : "=r"(r) : "f"(v));
    return r;
}

__device__ __forceinline__ void cp16(uint32_t dst, const void* src) {
    asm volatile("cp.async.cg.shared.global [%0], [%1], 16;" :: "r"(dst), "l"(src));
}

__device__ __forceinline__ void mma_tf32(float c[4], uint32_t a0, uint32_t a1,
                                         uint32_t a2, uint32_t a3,
                                         uint32_t b0, uint32_t b1) {
    asm volatile(
        "mma.sync.aligned.m16n8k8.row.col.f32.tf32.tf32.f32 "
        "{%0,%1,%2,%3}, {%4,%5,%6,%7}, {%8,%9}, {%0,%1,%2,%3};"
        : "+f"(c[0]), "+f"(c[1]), "+f"(c[2]), "+f"(c[3])
        : "r"(a0), "r"(a1), "r"(a2), "r"(a3), "r"(b0), "r"(b1));
}

__device__ __forceinline__ long long esz_get(const void* esz, int i, bool is64) {
    if (is64) return reinterpret_cast<const long long*>(esz)[i];
    return (long long)reinterpret_cast<const int*>(esz)[i];
}

__global__ void __launch_bounds__(NTHREADS, 1)
moe_mma_kernel(const float* __restrict__ X,
               const float* __restrict__ W,
               const void* __restrict__ expert_size,
               float* __restrict__ Y,
               long long total_tokens)
{
    extern __shared__ float smem[];
    float* Bf = smem;
    float* As = smem + BF_FLOATS;
    const uint32_t Bf_u32 = smem_u32(Bf);

    const int tid  = threadIdx.x;
    const int wid  = tid >> 5;
    const int lane = tid & 31;
    const int g    = lane >> 2;
    const int tig  = lane & 3;

    const int gid  = wid >> 3;              // group 0..2
    const int gwid = wid & 7;               // warp within group
    const int gtid = tid & 255;             // thread within group
    const int wm   = gwid >> 2;             // 0..1 (32-row M half)
    const int wn4  = gwid & 3;              // 0..3 (32-col N quarter)

    float* Ag = As + gid * (TT * KP);       // group's single A buffer
    const uint32_t Ag_u32 = smem_u32(Ag);

    const int e    = blockIdx.x / CPE;
    const int slot = blockIdx.x % CPE;

    // expert_size dtype sniff (declared i64; JAX x64-off delivers i32).
    const long long probe = reinterpret_cast<const long long*>(expert_size)[0];
    const bool is64 = (probe >= 0 && probe <= total_tokens);

    long long rb = 0;
    for (int i = 0; i < e; i++) rb += esz_get(expert_size, i, is64);
    long long esize = esz_get(expert_size, e, is64);
    if (rb < 0) rb = 0;
    if (rb > total_tokens) rb = total_tokens;
    if (esize < 0) esize = 0;
    if (rb + esize > total_tokens) esize = total_tokens - rb;

    const int etiles = (int)(esize / TT);
    const int q0 = etiles / CPE, r0c = etiles % CPE;
    const int tpc = q0 + (slot < r0c ? 1 : 0);
    const int t0  = slot * q0 + (slot < r0c ? slot : r0c);
    // Group takes tiles gid, gid+3, gid+6, ...
    const int gtpc = (tpc > gid) ? (tpc - gid + GROUPS - 1) / GROUPS : 0;

    // ---- Stage W_e into FRAGMENT-order SMEM (tf32 RN), all threads ----
    // Entry (vwn4, vks, c, l): float4 = {b0(nb=2c), b1(2c), b0(2c+1), b1(2c+1)}
    // with vg=l>>2, vtig=l&3, k=vks*8+vtig, n = vwn4*32 + nb*8 + vg.
    if (tpc > 0) {
        const float* wp = W + (size_t)e * ND * KD;
        for (int q = tid; q < 4 * 16 * 2 * 32; q += NTHREADS) {
            int l    = q & 31;
            int c    = (q >> 5) & 1;
            int vks  = (q >> 6) & 15;
            int vwn4 = q >> 10;
            int vg = l >> 2, vtig = l & 3;
            int k  = vks * 8 + vtig;
            int n0 = vwn4 * 32 + (2 * c) * 8 + vg;
            int n1 = n0 + 8;
            uint32_t f0 = f2tf32(wp[n0 * KD + k]);
            uint32_t f1 = f2tf32(wp[n0 * KD + k + 4]);
            uint32_t f2 = f2tf32(wp[n1 * KD + k]);
            uint32_t f3 = f2tf32(wp[n1 * KD + k + 4]);
            uint32_t a = Bf_u32 + (uint32_t)q * 16u;
            asm volatile("st.shared.v4.b32 [%0], {%1,%2,%3,%4};"
                         :: "r"(a), "r"(f0), "r"(f1), "r"(f2), "r"(f3) : "memory");
        }
    }

    // ---- Group's prefetch of its first tile ----
    if (gtpc > 0) {
        const int tile0 = t0 + gid;
        const float4* xp = reinterpret_cast<const float4*>(
            X + (rb + (long long)tile0 * TT) * KD);
        for (int q = gtid; q < TT * KD / 4; q += 256) {
            int r = q >> 5, c4 = (q & 31) << 2;
            cp16(Ag_u32 + (uint32_t)(r * KP + c4) * 4u, xp + q);
        }
    }
    asm volatile("cp.async.commit_group;" ::: "memory");

    __syncthreads();                        // Bf visible; groups diverge now
    if (gtpc == 0) return;

    const int row_a = wm * 32 + g;          // first A row within group-tile
    const int colb0 = wn4 * 32;
    const uint32_t bf_warp = Bf_u32 + (uint32_t)wn4 * 16384u + (uint32_t)lane * 16u;
    const int bar_id = gid + 1;

    for (int it = 0; it < gtpc; it++) {
        const int tile = t0 + gid + GROUPS * it;

        asm volatile("cp.async.wait_group 0;" ::: "memory");
        asm volatile("bar.sync %0, 256;" :: "r"(bar_id) : "memory");

        // ---- Compute: warp-tile 32x32 (R15 core) ----
        const float* A0t = Ag + tig;
        float acc[8][4];
        #pragma unroll
        for (int p = 0; p < 8; p++)
            #pragma unroll
            for (int i = 0; i < 4; i++) acc[p][i] = 0.0f;

        #pragma unroll
        for (int ks = 0; ks < 16; ks++) {
            const int k = ks * 8;
            uint32_t aF[8];
            #pragma unroll
            for (int mc = 0; mc < 2; mc++) {
                const float* Ar = A0t + (row_a + mc * 16) * KP + k;
                aF[mc * 4 + 0] = f2tf32(Ar[0]);
                aF[mc * 4 + 1] = f2tf32(Ar[8 * KP]);
                aF[mc * 4 + 2] = f2tf32(Ar[4]);
                aF[mc * 4 + 3] = f2tf32(Ar[8 * KP + 4]);
            }
            uint32_t bF[8];
            const uint32_t bks = bf_warp + (uint32_t)ks * 1024u;
            #pragma unroll
            for (int c = 0; c < 2; c++) {
                asm volatile("ld.shared.v4.b32 {%0,%1,%2,%3}, [%4];"
                             : "=r"(bF[c * 4 + 0]), "=r"(bF[c * 4 + 1]),
                               "=r"(bF[c * 4 + 2]), "=r"(bF[c * 4 + 3])
                             : "r"(bks + (uint32_t)c * 512u));
            }
            #pragma unroll
            for (int mc = 0; mc < 2; mc++)
                #pragma unroll
                for (int nb = 0; nb < 4; nb++) {
                    // v4 c=nb>>1 holds pairs for nb=2c (+0,+1) and nb=2c+1 (+2,+3)
                    const int bi = (nb >> 1) * 4 + (nb & 1) * 2;
                    mma_tf32(acc[mc * 4 + nb],
                             aF[mc * 4 + 0], aF[mc * 4 + 1],
                             aF[mc * 4 + 2], aF[mc * 4 + 3],
                             bF[bi], bF[bi + 1]);
                }
        }

        // All group warps done READING A -> safe to overwrite.
        asm volatile("bar.sync %0, 256;" :: "r"(bar_id) : "memory");

        // Prefetch this group's next tile (overlaps epilogue + other groups).
        if (it + 1 < gtpc) {
            const int ntile = tile + GROUPS;
            const float4* xp = reinterpret_cast<const float4*>(
                X + (rb + (long long)ntile * TT) * KD);
            for (int q = gtid; q < TT * KD / 4; q += 256) {
                int r = q >> 5, c4 = (q & 31) << 2;
                cp16(Ag_u32 + (uint32_t)(r * KP + c4) * 4u, xp + q);
            }
        }
        asm volatile("cp.async.commit_group;" ::: "memory");

        // ---- Epilogue: st.global.v2 (full 32B sectors) ----
        {
            const long long tile_row = rb + (long long)tile * TT;
            #pragma unroll
            for (int mc = 0; mc < 2; mc++) {
                float* dst0 = Y + (tile_row + row_a + mc * 16)     * ND + colb0 + tig * 2;
                float* dst1 = Y + (tile_row + row_a + mc * 16 + 8) * ND + colb0 + tig * 2;
                #pragma unroll
                for (int nb = 0; nb < 4; nb++) {
                    float2 v0 = make_float2(acc[mc * 4 + nb][0], acc[mc * 4 + nb][1]);
                    float2 v1 = make_float2(acc[mc * 4 + nb][2], acc[mc * 4 + nb][3]);
                    *reinterpret_cast<float2*>(dst0 + nb * 8) = v0;
                    *reinterpret_cast<float2*>(dst1 + nb * 8) = v1;
                }
            }
        }
    }
}

extern "C" void kernel_launch(void* const* d_in, const int* in_sizes, int n_in,
                              void* d_out, int out_size) {
    const float* X   = (const float*)d_in[0];
    const float* W   = (const float*)d_in[1];
    const void*  esz = d_in[2];
    float*       Y   = (float*)d_out;

    const long long total_tokens = (long long)in_sizes[0] / KD;

    cudaFuncSetAttribute(moe_mma_kernel,
                         cudaFuncAttributeMaxDynamicSharedMemorySize,
                         SMEM_FLOATS * (int)sizeof(float));

    moe_mma_kernel<<<NEXP * CPE, NTHREADS, SMEM_FLOATS * (int)sizeof(float)>>>(
        X, W, esz, Y, total_tokens);
}